// round 1
// baseline (speedup 1.0000x reference)
#include <cuda_runtime.h>
#include <math.h>

// ---------------- constants ----------------
#define TN   4096
#define NENV 32
#define TT   128
#define HID  256
#define NBLK_LSTM 128

// ---------------- scratch (device globals; no allocs allowed) ----------------
__device__ float g_out1[TN * 32 * 15 * 15];   // conv1 out  (118MB)
__device__ float g_out2[TN * 64 * 6 * 6];     // conv2 out
__device__ float g_out3[TN * 1024];           // conv3 out flattened
__device__ float g_feats[TN * 512];           // fc out
__device__ float g_gi[TN * 1024];             // precomputed gate inputs
__device__ float g_outs[TN * HID];            // all h_t
__device__ float g_hbuf[2][HID * NENV];       // transposed h double buffer [col][r]
__device__ unsigned int g_bar_arrive = 0;
__device__ unsigned int g_bar_gen = 0;

// ---------------- conv1: (TN,4,64,64) -> (TN,32,15,15), k=8, s=4 ----------------
__global__ void conv1_kernel(const float* __restrict__ x, const float* __restrict__ w,
                             const float* __restrict__ b, float* __restrict__ out) {
    extern __shared__ float sm[];
    float* xs = sm;            // 16384 floats
    float* ws = sm + 16384;    // 8192 floats, layout [oc][256]
    const int tid = threadIdx.x;
    const int img = blockIdx.x;

    const float4* xg = (const float4*)(x + (size_t)img * 16384);
    const float inv = 1.0f / 255.0f;
    for (int i = tid; i < 4096; i += 256) {
        float4 v = xg[i];
        v.x *= inv; v.y *= inv; v.z *= inv; v.w *= inv;
        ((float4*)xs)[i] = v;
    }
    for (int i = tid; i < 2048; i += 256)
        ((float4*)ws)[i] = ((const float4*)w)[i];
    __syncthreads();

    if (tid < 225) {
        const int py = tid / 15, px = tid % 15;
        float acc[32];
#pragma unroll
        for (int oc = 0; oc < 32; oc++) acc[oc] = 0.f;
        const float* xb = xs + py * 256 + px * 4;   // (py*4)*64 + px*4
#pragma unroll 1
        for (int ik = 0; ik < 32; ik++) {           // ik = ic*8 + ky
            const int ic = ik >> 3, ky = ik & 7;
            const float* xr = xb + ic * 4096 + ky * 64;
            float xv[8];
#pragma unroll
            for (int kx = 0; kx < 8; kx++) xv[kx] = xr[kx];
            const float* wr = ws + ik * 8;          // w[oc][ic*64+ky*8 + kx]
#pragma unroll
            for (int oc = 0; oc < 32; oc++) {
                const float4 w0 = *(const float4*)(wr + oc * 256);
                const float4 w1 = *(const float4*)(wr + oc * 256 + 4);
                acc[oc] += xv[0]*w0.x + xv[1]*w0.y + xv[2]*w0.z + xv[3]*w0.w
                         + xv[4]*w1.x + xv[5]*w1.y + xv[6]*w1.z + xv[7]*w1.w;
            }
        }
        float* op = out + (size_t)img * 7200 + tid;
#pragma unroll
        for (int oc = 0; oc < 32; oc++) {
            float v = acc[oc] + b[oc];
            op[oc * 225] = v > 0.f ? v : 0.f;
        }
    }
}

// ---------------- conv2: (TN,32,15,15) -> (TN,64,6,6), k=4, s=2 ----------------
__global__ void conv2_kernel(const float* __restrict__ in, const float* __restrict__ w,
                             const float* __restrict__ b, float* __restrict__ out) {
    extern __shared__ float sm[];
    float* xs = sm;            // 7200
    float* ws = sm + 7200;     // 32768, layout [oc][512]
    const int tid = threadIdx.x;
    const int img = blockIdx.x;

    for (int i = tid; i < 7200; i += 288) xs[i] = in[(size_t)img * 7200 + i];
    for (int i = tid; i < 8192; i += 288) ((float4*)ws)[i] = ((const float4*)w)[i];
    __syncthreads();

    const int pos = tid % 36, ocg = tid / 36;   // 288 = 8*36 exact
    const int oy = pos / 6, ox = pos % 6;
    float acc[8];
#pragma unroll
    for (int j = 0; j < 8; j++) acc[j] = 0.f;
    const float* xb = xs + oy * 30 + ox * 2;
#pragma unroll 1
    for (int ik = 0; ik < 128; ik++) {          // ik = ic*4 + ky
        const int ic = ik >> 2, ky = ik & 3;
        const float* xr = xb + ic * 225 + ky * 15;
        const float x0 = xr[0], x1 = xr[1], x2 = xr[2], x3 = xr[3];
        const float* wr = ws + ocg * 8 * 512 + ik * 4;
#pragma unroll
        for (int j = 0; j < 8; j++) {
            const float4 wv = *(const float4*)(wr + j * 512);
            acc[j] += x0*wv.x + x1*wv.y + x2*wv.z + x3*wv.w;
        }
    }
    float* op = out + (size_t)img * 2304 + pos;
#pragma unroll
    for (int j = 0; j < 8; j++) {
        const int oc = ocg * 8 + j;
        float v = acc[j] + b[oc];
        op[oc * 36] = v > 0.f ? v : 0.f;
    }
}

// ---------------- conv3: (TN,64,6,6) -> (TN,64,4,4), k=3, s=1 ; 2 imgs/block ----
__global__ void conv3_kernel(const float* __restrict__ in, const float* __restrict__ w,
                             const float* __restrict__ b, float* __restrict__ out) {
    extern __shared__ float sm[];
    float* xs = sm;            // 2*2304
    float* ws = sm + 4608;     // 36864, layout [oc][576]
    const int tid = threadIdx.x;
    const int blk = blockIdx.x;

    for (int i = tid; i < 4608; i += 256) xs[i] = in[(size_t)blk * 4608 + i];
    for (int i = tid; i < 9216; i += 256) ((float4*)ws)[i] = ((const float4*)w)[i];
    __syncthreads();

    const int half = tid >> 7, t = tid & 127;
    const int pos = t & 15, ocg = t >> 4;
    const int oy = pos >> 2, ox = pos & 3;
    const int img = blk * 2 + half;
    float acc[8];
#pragma unroll
    for (int j = 0; j < 8; j++) acc[j] = 0.f;
    const float* xb = xs + half * 2304 + oy * 6 + ox;
#pragma unroll 1
    for (int ic = 0; ic < 64; ic++) {
        const float* xc = xb + ic * 36;
        const float* wc = ws + ocg * 8 * 576 + ic * 9;
#pragma unroll
        for (int ky = 0; ky < 3; ky++) {
            const float x0 = xc[ky*6+0], x1 = xc[ky*6+1], x2 = xc[ky*6+2];
            const float* wr = wc + ky * 3;
#pragma unroll
            for (int j = 0; j < 8; j++) {
                const float* wj = wr + j * 576;
                acc[j] += x0*wj[0] + x1*wj[1] + x2*wj[2];
            }
        }
    }
    float* op = out + (size_t)img * 1024 + pos;
#pragma unroll
    for (int j = 0; j < 8; j++) {
        const int oc = ocg * 8 + j;
        float v = acc[j] + b[oc];
        op[oc * 16] = v > 0.f ? v : 0.f;   // flatten = c*16 + y*4 + x
    }
}

// ---------------- tiled NT GEMM: C[MxN] = act(A[MxK] * B[NxK]^T + b1 + b2) ------
__global__ void gemm_nt(const float* __restrict__ A, const float* __restrict__ B,
                        const float* __restrict__ bias1, const float* __restrict__ bias2,
                        float* __restrict__ C, int M, int N, int K, int do_relu) {
    __shared__ float As[16][64];
    __shared__ float Bs[16][64];
    const int tid = threadIdx.x;
    const int m0 = blockIdx.y * 64, n0 = blockIdx.x * 64;
    const int lr = tid >> 2, lk = tid & 3;
    const int tx = tid & 15, ty = tid >> 4;
    const float* Ap = A + (size_t)(m0 + lr) * K + lk * 4;
    const float* Bp = B + (size_t)(n0 + lr) * K + lk * 4;
    float c[4][4];
#pragma unroll
    for (int i = 0; i < 4; i++)
#pragma unroll
        for (int j = 0; j < 4; j++) c[i][j] = 0.f;

    for (int k0 = 0; k0 < K; k0 += 16) {
        const float4 av = *(const float4*)(Ap + k0);
        const float4 bv = *(const float4*)(Bp + k0);
        __syncthreads();
        As[lk*4+0][lr] = av.x; As[lk*4+1][lr] = av.y; As[lk*4+2][lr] = av.z; As[lk*4+3][lr] = av.w;
        Bs[lk*4+0][lr] = bv.x; Bs[lk*4+1][lr] = bv.y; Bs[lk*4+2][lr] = bv.z; Bs[lk*4+3][lr] = bv.w;
        __syncthreads();
#pragma unroll
        for (int kk = 0; kk < 16; kk++) {
            const float4 a = *(const float4*)&As[kk][ty * 4];
            const float4 b = *(const float4*)&Bs[kk][tx * 4];
            const float avr[4] = {a.x, a.y, a.z, a.w};
            const float bvr[4] = {b.x, b.y, b.z, b.w};
#pragma unroll
            for (int i = 0; i < 4; i++)
#pragma unroll
                for (int j = 0; j < 4; j++) c[i][j] += avr[i] * bvr[j];
        }
    }
    const int m = m0 + ty * 4, n = n0 + tx * 4;
    float bb[4];
#pragma unroll
    for (int j = 0; j < 4; j++) {
        float v = bias1 ? bias1[n + j] : 0.f;
        if (bias2) v += bias2[n + j];
        bb[j] = v;
    }
#pragma unroll
    for (int i = 0; i < 4; i++) {
        float4 v;
        float* vp = &v.x;
#pragma unroll
        for (int j = 0; j < 4; j++) {
            float u = c[i][j] + bb[j];
            if (do_relu) u = u > 0.f ? u : 0.f;
            vp[j] = u;
        }
        *(float4*)&C[(size_t)(m + i) * N + n] = v;
    }
}

// ---------------- h0 transpose into double buffer ----------------
__global__ void init_h_kernel(const float* __restrict__ h0) {
    const int i = blockIdx.x * blockDim.x + threadIdx.x;  // 8192
    const int r = i / HID, col = i % HID;
    g_hbuf[0][col * NENV + r] = h0[i];
}

// ---------------- persistent LSTM over T steps ----------------
__device__ __forceinline__ void grid_bar(unsigned int target) {
    __threadfence();
    __syncthreads();
    if (threadIdx.x == 0) {
        if (atomicAdd(&g_bar_arrive, 1) == (unsigned)gridDim.x - 1) {
            g_bar_arrive = 0;
            __threadfence();
            atomicExch(&g_bar_gen, target);
        } else {
            while ((int)(*(volatile unsigned int*)&g_bar_gen - target) < 0)
                __nanosleep(64);
        }
        __threadfence();
    }
    __syncthreads();
}

__global__ void lstm_kernel(const float* __restrict__ gi, const float* __restrict__ done,
                            const float* __restrict__ c0, const float* __restrict__ wh,
                            float* __restrict__ outs) {
    __shared__ __align__(16) float hs[HID * NENV];  // [col][r], 32KB
    __shared__ float whs[8 * HID];                  // 8KB
    __shared__ float gsm[8 * NENV];
    __shared__ float cs[2 * NENV];
    __shared__ __align__(16) float ms[NENV];
    __shared__ unsigned int s_base;

    const int tid = threadIdx.x, b = blockIdx.x;
    const int w = tid >> 5, lane = tid & 31;
    const int G = (w & 3) * HID + 2 * b + (w >> 2);  // gate row this warp owns

    for (int k = lane; k < HID; k += 32) whs[w * HID + k] = wh[(size_t)G * HID + k];
    if (tid < 64) {
        const int hcl = tid >> 5, r = tid & 31;
        cs[tid] = c0[r * HID + 2 * b + hcl];
    }
    if (tid == 0) s_base = g_bar_gen;
    __syncthreads();
    const unsigned int base = s_base;

    for (int t = 0; t < TT; t++) {
        const float giv = gi[(size_t)(t * NENV + lane) * 1024 + G];  // prefetch early
        const float* hsrc = g_hbuf[t & 1];
        if (tid < NENV) ms[tid] = 1.0f - done[t * NENV + tid];
        __syncthreads();
        // load full h (masked) into smem; layout [col][r], fully coalesced
        for (int i = tid; i < (HID * NENV) / 4; i += 256) {
            float4 v = ((const float4*)hsrc)[i];
            const float4 mv = ((const float4*)ms)[i & 7];
            v.x *= mv.x; v.y *= mv.y; v.z *= mv.z; v.w *= mv.w;
            ((float4*)hs)[i] = v;
        }
        __syncthreads();

        // gates[r=lane][G] = gi + h[r,:] . wh[G,:]
        float acc = giv;
        const float* wr = whs + w * HID;
#pragma unroll 8
        for (int k = 0; k < HID; k += 4) {
            const float4 wv = *(const float4*)(wr + k);
            acc += hs[(k + 0) * NENV + lane] * wv.x
                 + hs[(k + 1) * NENV + lane] * wv.y
                 + hs[(k + 2) * NENV + lane] * wv.z
                 + hs[(k + 3) * NENV + lane] * wv.w;
        }
        gsm[w * NENV + lane] = acc;
        __syncthreads();

        float* hdst = g_hbuf[(t + 1) & 1];
        if (tid < 64) {
            const int hcl = tid >> 5, r = tid & 31;
            const float gi_ = gsm[(hcl * 4 + 0) * NENV + r];
            const float gf_ = gsm[(hcl * 4 + 1) * NENV + r];
            const float gg_ = gsm[(hcl * 4 + 2) * NENV + r];
            const float go_ = gsm[(hcl * 4 + 3) * NENV + r];
            const float iv = 1.f / (1.f + expf(-gi_));
            const float fv = 1.f / (1.f + expf(-gf_));
            const float ov = 1.f / (1.f + expf(-go_));
            const float gv = tanhf(gg_);
            const float c = fv * (cs[tid] * ms[r]) + iv * gv;
            cs[tid] = c;
            const float h = ov * tanhf(c);
            const int hc = 2 * b + hcl;
            hdst[hc * NENV + r] = h;
            outs[(size_t)(t * NENV + r) * HID + hc] = h;
        }
        grid_bar(base + t + 1);
    }
}

// ---------------- actor/critic heads ----------------
__global__ void heads_kernel(const float* __restrict__ outs,
                             const float* __restrict__ aw, const float* __restrict__ ab,
                             const float* __restrict__ cw, const float* __restrict__ cb,
                             float* __restrict__ out) {
    __shared__ float hsm[32 * HID];
    const int tid = threadIdx.x, row0 = blockIdx.x * 32;
    for (int i = tid; i < 32 * HID; i += 256) hsm[i] = outs[(size_t)row0 * HID + i];
    __syncthreads();
    for (int o = tid; o < 32 * 19; o += 256) {
        const int r = o / 19, j = o % 19;
        const float* wp = (j < 18) ? (aw + j * HID) : cw;
        const float bias = (j < 18) ? ab[j] : cb[0];
        const float4* h4 = (const float4*)(hsm + r * HID);
        const float4* w4 = (const float4*)wp;
        float acc = 0.f;
#pragma unroll 8
        for (int k = 0; k < HID / 4; k++) {
            const float4 hv = h4[k];
            const float4 wv = __ldg(&w4[k]);
            acc += hv.x*wv.x + hv.y*wv.y + hv.z*wv.z + hv.w*wv.w;
        }
        out[(size_t)(row0 + r) * 19 + j] = acc + bias;
    }
}

// ---------------- launch ----------------
extern "C" void kernel_launch(void* const* d_in, const int* in_sizes, int n_in,
                              void* d_out, int out_size) {
    const float* x    = (const float*)d_in[0];
    const float* done = (const float*)d_in[1];
    const float* h0   = (const float*)d_in[2];
    const float* c0   = (const float*)d_in[3];
    const float* c1w  = (const float*)d_in[4];
    const float* c1b  = (const float*)d_in[5];
    const float* c2w  = (const float*)d_in[6];
    const float* c2b  = (const float*)d_in[7];
    const float* c3w  = (const float*)d_in[8];
    const float* c3b  = (const float*)d_in[9];
    const float* fcw  = (const float*)d_in[10];
    const float* fcb  = (const float*)d_in[11];
    const float* wi   = (const float*)d_in[12];
    const float* wh   = (const float*)d_in[13];
    const float* bi   = (const float*)d_in[14];
    const float* bh   = (const float*)d_in[15];
    const float* aw   = (const float*)d_in[16];
    const float* ab   = (const float*)d_in[17];
    const float* cw   = (const float*)d_in[18];
    const float* cb   = (const float*)d_in[19];
    float* out = (float*)d_out;

    cudaFuncSetAttribute(conv1_kernel, cudaFuncAttributeMaxDynamicSharedMemorySize, 98304);
    cudaFuncSetAttribute(conv2_kernel, cudaFuncAttributeMaxDynamicSharedMemorySize, 159872);
    cudaFuncSetAttribute(conv3_kernel, cudaFuncAttributeMaxDynamicSharedMemorySize, 165888);

    float* out1;  cudaGetSymbolAddress((void**)&out1,  g_out1);
    float* out2;  cudaGetSymbolAddress((void**)&out2,  g_out2);
    float* out3;  cudaGetSymbolAddress((void**)&out3,  g_out3);
    float* feats; cudaGetSymbolAddress((void**)&feats, g_feats);
    float* gi;    cudaGetSymbolAddress((void**)&gi,    g_gi);
    float* outs;  cudaGetSymbolAddress((void**)&outs,  g_outs);

    conv1_kernel<<<TN, 256, 98304>>>(x, c1w, c1b, out1);
    conv2_kernel<<<TN, 288, 159872>>>(out1, c2w, c2b, out2);
    conv3_kernel<<<TN / 2, 256, 165888>>>(out2, c3w, c3b, out3);
    gemm_nt<<<dim3(512 / 64, TN / 64), 256>>>(out3, fcw, fcb, nullptr, feats, TN, 512, 1024, 1);
    gemm_nt<<<dim3(1024 / 64, TN / 64), 256>>>(feats, wi, bi, bh, gi, TN, 1024, 512, 0);
    init_h_kernel<<<32, 256>>>(h0);
    lstm_kernel<<<NBLK_LSTM, 256>>>(gi, done, c0, wh, outs);
    heads_kernel<<<TN / 32, 256>>>(outs, aw, ab, cw, cb, out);
}

// round 2
// speedup vs baseline: 1.1217x; 1.1217x over previous
#include <cuda_runtime.h>
#include <math.h>

// ---------------- constants ----------------
#define TN   4096
#define NENV 32
#define TT   128
#define HID  256
#define NBLK_LSTM 128

typedef unsigned long long ull;

// ---------------- packed f32x2 helpers ----------------
__device__ __forceinline__ ull pk2(float lo, float hi) {
    ull r; asm("mov.b64 %0,{%1,%2};" : "=l"(r) : "f"(lo), "f"(hi)); return r;
}
__device__ __forceinline__ void unpk2(ull v, float& lo, float& hi) {
    asm("mov.b64 {%0,%1},%2;" : "=f"(lo), "=f"(hi) : "l"(v));
}
__device__ __forceinline__ ull ffma2(ull a, ull b, ull c) {
    ull d; asm("fma.rn.f32x2 %0,%1,%2,%3;" : "=l"(d) : "l"(a), "l"(b), "l"(c)); return d;
}
__device__ __forceinline__ ull fmul2(ull a, ull b) {
    ull d; asm("mul.rn.f32x2 %0,%1,%2;" : "=l"(d) : "l"(a), "l"(b)); return d;
}
__device__ __forceinline__ float psum(ull v) {
    float lo, hi; unpk2(v, lo, hi); return lo + hi;
}

// ---------------- scratch (device globals; no allocs allowed) ----------------
__device__ float g_out1[TN * 32 * 256];       // conv1 out, rows padded 15->16 (134MB)
__device__ float g_out2[TN * 64 * 6 * 6];     // conv2 out
__device__ float g_out3[TN * 1024];           // conv3 out flattened
__device__ float g_feats[TN * 512];           // fc out
__device__ float g_gi[TN * 1024];             // gate inputs [t*32+r][G]
__device__ float g_gt[TN * 1024];             // gate inputs transposed [t][G][r]
__device__ float g_outs[TN * HID];            // all h_t
__device__ ull   g_hbuf[2][128 * NENV];       // packed h pairs [k/2][r], double buffer
__device__ unsigned int g_bar_arrive = 0;
__device__ unsigned int g_bar_gen = 0;

// ---------------- conv1: (TN,4,64,64) -> (TN,32,15,15pad16), k=8, s=4 ----------
__global__ __launch_bounds__(256) void conv1_kernel(
        const float* __restrict__ x, const float* __restrict__ w,
        const float* __restrict__ b, float* __restrict__ out) {
    extern __shared__ float sm[];
    float* xs = sm;            // 16384 floats
    float* ws = sm + 16384;    // 8192 floats, layout [oc][256]
    const int tid = threadIdx.x;
    const int img = blockIdx.x;

    const float4* xg = (const float4*)(x + (size_t)img * 16384);
    const float inv = 1.0f / 255.0f;
    for (int i = tid; i < 4096; i += 256) {
        float4 v = xg[i];
        v.x *= inv; v.y *= inv; v.z *= inv; v.w *= inv;
        ((float4*)xs)[i] = v;
    }
    for (int i = tid; i < 2048; i += 256)
        ((float4*)ws)[i] = ((const float4*)w)[i];
    __syncthreads();

    if (tid < 225) {
        const int py = tid / 15, px = tid % 15;
        ull acc[32];
#pragma unroll
        for (int oc = 0; oc < 32; oc++) acc[oc] = 0ull;
        const float* xb = xs + py * 256 + px * 4;
#pragma unroll 1
        for (int ik = 0; ik < 32; ik++) {           // ik = ic*8 + ky
            const int ic = ik >> 3, ky = ik & 7;
            const float* xr = xb + ic * 4096 + ky * 64;     // 16B aligned
            const ulonglong2 xa = ((const ulonglong2*)xr)[0];
            const ulonglong2 xc = ((const ulonglong2*)xr)[1];
            const float* wr = ws + ik * 8;          // 32B aligned per oc
#pragma unroll
            for (int oc = 0; oc < 32; oc++) {
                const ulonglong2 w0 = ((const ulonglong2*)(wr + oc * 256))[0];
                const ulonglong2 w1 = ((const ulonglong2*)(wr + oc * 256))[1];
                ull a = acc[oc];
                a = ffma2(xa.x, w0.x, a);
                a = ffma2(xa.y, w0.y, a);
                a = ffma2(xc.x, w1.x, a);
                a = ffma2(xc.y, w1.y, a);
                acc[oc] = a;
            }
        }
        float* op = out + (size_t)img * 8192 + py * 16 + px;
#pragma unroll
        for (int oc = 0; oc < 32; oc++) {
            float v = psum(acc[oc]) + b[oc];
            op[oc * 256] = v > 0.f ? v : 0.f;
        }
    }
}

// ---------------- conv2: (TN,32,16x16pad) -> (TN,64,6,6), k=4, s=2 --------------
__global__ __launch_bounds__(288) void conv2_kernel(
        const float* __restrict__ in, const float* __restrict__ w,
        const float* __restrict__ b, float* __restrict__ out) {
    extern __shared__ float sm[];
    float* xs = sm;            // 8192 floats (padded layout)
    float* ws = sm + 8192;     // 32768 floats, layout [oc][512]
    const int tid = threadIdx.x;
    const int img = blockIdx.x;

    const float4* in4 = (const float4*)(in + (size_t)img * 8192);
    for (int i = tid; i < 2048; i += 288) ((float4*)xs)[i] = in4[i];
    for (int i = tid; i < 8192; i += 288) ((float4*)ws)[i] = ((const float4*)w)[i];
    __syncthreads();

    const int pos = tid % 36, ocg = tid / 36;   // 288 = 8*36 exact
    const int oy = pos / 6, ox = pos % 6;
    ull acc[8];
#pragma unroll
    for (int j = 0; j < 8; j++) acc[j] = 0ull;
    const float* xb = xs + oy * 32 + ox * 2;    // padded: row stride 16, ch stride 256
#pragma unroll 1
    for (int ik = 0; ik < 128; ik++) {          // ik = ic*4 + ky
        const int ic = ik >> 2, ky = ik & 3;
        const float* xr = xb + ic * 256 + ky * 16;  // even offset -> 8B aligned
        const ull x01 = ((const ull*)xr)[0];
        const ull x23 = ((const ull*)xr)[1];
        const float* wr = ws + ocg * 8 * 512 + ik * 4;  // 16B aligned
#pragma unroll
        for (int j = 0; j < 8; j++) {
            const ulonglong2 wv = *(const ulonglong2*)(wr + j * 512);
            ull a = acc[j];
            a = ffma2(x01, wv.x, a);
            a = ffma2(x23, wv.y, a);
            acc[j] = a;
        }
    }
    float* op = out + (size_t)img * 2304 + pos;
#pragma unroll
    for (int j = 0; j < 8; j++) {
        const int oc = ocg * 8 + j;
        float v = psum(acc[j]) + b[oc];
        op[oc * 36] = v > 0.f ? v : 0.f;
    }
}

// ---------------- conv3: (TN,64,6,6) -> (TN,64,4,4), k=3, s=1 ; 2 imgs/block ----
__global__ __launch_bounds__(256) void conv3_kernel(
        const float* __restrict__ in, const float* __restrict__ w,
        const float* __restrict__ b, float* __restrict__ out) {
    extern __shared__ float sm[];
    float* xs = sm;            // 2*2304
    float* ws = sm + 4608;     // 64*768 floats, layout [oc][ic*12 + ky*4 + kx], kx pad=0
    const int tid = threadIdx.x;
    const int blk = blockIdx.x;

    for (int i = tid; i < 4608; i += 256) xs[i] = in[(size_t)blk * 4608 + i];
    // zero pad slots
    for (int i = tid; i < 64 * 64 * 3; i += 256) {
        const int oc = i / 192, rem = i % 192;     // rem = ic*3+ky
        const int ic = rem / 3, ky = rem % 3;
        ws[oc * 768 + ic * 12 + ky * 4 + 3] = 0.f;
    }
    for (int i = tid; i < 64 * 576; i += 256) {
        const int oc = i / 576, rem = i % 576;
        const int ic = rem / 9, kk = rem % 9;
        const int ky = kk / 3, kx = kk % 3;
        ws[oc * 768 + ic * 12 + ky * 4 + kx] = w[i];
    }
    __syncthreads();

    const int half = tid >> 7, t = tid & 127;
    const int pos = t & 15, ocg = t >> 4;
    const int oy = pos >> 2, ox = pos & 3;
    const int img = blk * 2 + half;
    ull acc[8];
#pragma unroll
    for (int j = 0; j < 8; j++) acc[j] = 0ull;
    const float* xb = xs + half * 2304 + oy * 6 + ox;
#pragma unroll 1
    for (int ic = 0; ic < 64; ic++) {
        const float* xc = xb + ic * 36;
        const float* wc = ws + ocg * 8 * 768 + ic * 12;
#pragma unroll
        for (int ky = 0; ky < 3; ky++) {
            const float x0 = xc[ky*6+0], x1 = xc[ky*6+1], x2 = xc[ky*6+2];
            const ull xp01 = pk2(x0, x1);
            const ull xp2  = pk2(x2, 0.f);
            const float* wr = wc + ky * 4;          // 16B aligned
#pragma unroll
            for (int j = 0; j < 8; j++) {
                const ulonglong2 wv = *(const ulonglong2*)(wr + j * 768);
                ull a = acc[j];
                a = ffma2(xp01, wv.x, a);
                a = ffma2(xp2,  wv.y, a);
                acc[j] = a;
            }
        }
    }
    float* op = out + (size_t)img * 1024 + pos;
#pragma unroll
    for (int j = 0; j < 8; j++) {
        const int oc = ocg * 8 + j;
        float v = psum(acc[j]) + b[oc];
        op[oc * 16] = v > 0.f ? v : 0.f;   // flatten = c*16 + y*4 + x
    }
}

// ---------------- tiled NT GEMM (FFMA2): C = act(A[MxK] B[NxK]^T + b1 + b2) -----
// 128x64 tile, 256 threads, thread micro-tile = 8 rows (4 packed pairs) x 4 cols
__global__ __launch_bounds__(256) void gemm_nt(
        const float* __restrict__ A, const float* __restrict__ B,
        const float* __restrict__ bias1, const float* __restrict__ bias2,
        float* __restrict__ C, int M, int N, int K, int do_relu) {
    __shared__ __align__(16) float As[16][128];   // [k][m]
    __shared__ __align__(16) ull   Bs[16][64];    // [k][n] pre-duplicated pairs
    const int tid = threadIdx.x;
    const int m0 = blockIdx.y * 128, n0 = blockIdx.x * 64;
    const int arow = tid >> 1, ahalf = tid & 1;
    const int brow = tid >> 2, bq = tid & 3;
    const int ty = tid >> 4, tx = tid & 15;
    const float* Ap = A + (size_t)(m0 + arow) * K + ahalf * 8;
    const float* Bp = B + (size_t)(n0 + brow) * K + bq * 4;

    ull acc[4][4];
#pragma unroll
    for (int i = 0; i < 4; i++)
#pragma unroll
        for (int j = 0; j < 4; j++) acc[i][j] = 0ull;

    for (int k0 = 0; k0 < K; k0 += 16) {
        const float4 a0 = *(const float4*)(Ap + k0);
        const float4 a1 = *(const float4*)(Ap + k0 + 4);
        const float4 bv = *(const float4*)(Bp + k0);
        __syncthreads();
        As[ahalf*8+0][arow] = a0.x; As[ahalf*8+1][arow] = a0.y;
        As[ahalf*8+2][arow] = a0.z; As[ahalf*8+3][arow] = a0.w;
        As[ahalf*8+4][arow] = a1.x; As[ahalf*8+5][arow] = a1.y;
        As[ahalf*8+6][arow] = a1.z; As[ahalf*8+7][arow] = a1.w;
        Bs[bq*4+0][brow] = pk2(bv.x, bv.x);
        Bs[bq*4+1][brow] = pk2(bv.y, bv.y);
        Bs[bq*4+2][brow] = pk2(bv.z, bv.z);
        Bs[bq*4+3][brow] = pk2(bv.w, bv.w);
        __syncthreads();
#pragma unroll
        for (int kk = 0; kk < 16; kk++) {
            const ulonglong2 ap0 = ((const ulonglong2*)&As[kk][0])[ty*2];
            const ulonglong2 ap1 = ((const ulonglong2*)&As[kk][0])[ty*2+1];
            const ulonglong2 bp0 = ((const ulonglong2*)&Bs[kk][0])[tx*2];
            const ulonglong2 bp1 = ((const ulonglong2*)&Bs[kk][0])[tx*2+1];
            const ull ar[4] = {ap0.x, ap0.y, ap1.x, ap1.y};
            const ull br[4] = {bp0.x, bp0.y, bp1.x, bp1.y};
#pragma unroll
            for (int i = 0; i < 4; i++)
#pragma unroll
                for (int j = 0; j < 4; j++)
                    acc[i][j] = ffma2(ar[i], br[j], acc[i][j]);
        }
    }

    const int n = n0 + tx * 4;
    float bb[4];
#pragma unroll
    for (int j = 0; j < 4; j++) {
        float v = bias1 ? bias1[n + j] : 0.f;
        if (bias2) v += bias2[n + j];
        bb[j] = v;
    }
    const int mrow = m0 + ty * 8;
#pragma unroll
    for (int i = 0; i < 4; i++) {
        float4 v0, v1;
        float* p0 = &v0.x; float* p1 = &v1.x;
#pragma unroll
        for (int j = 0; j < 4; j++) {
            float lo, hi; unpk2(acc[i][j], lo, hi);
            float u0 = lo + bb[j], u1 = hi + bb[j];
            if (do_relu) { u0 = u0 > 0.f ? u0 : 0.f; u1 = u1 > 0.f ? u1 : 0.f; }
            p0[j] = u0; p1[j] = u1;
        }
        *(float4*)&C[(size_t)(mrow + 2*i + 0) * N + n] = v0;
        *(float4*)&C[(size_t)(mrow + 2*i + 1) * N + n] = v1;
    }
}

// ---------------- gi transpose: [t*32+r][G] -> [t][G][r] ----------------
__global__ void gi_transpose(const float* __restrict__ gi, float* __restrict__ gt) {
    __shared__ float tile[32][33];
    const int t = blockIdx.x, gb = blockIdx.y;
    const int tx = threadIdx.x, ty = threadIdx.y;      // (32, 8)
    for (int rr = ty; rr < 32; rr += 8)
        tile[rr][tx] = gi[(size_t)(t * 32 + rr) * 1024 + gb * 32 + tx];
    __syncthreads();
    for (int gg = ty; gg < 32; gg += 8)
        gt[(size_t)(t * 1024 + gb * 32 + gg) * 32 + tx] = tile[tx][gg];
}

// ---------------- h0 into packed double buffer ----------------
__global__ void init_h_kernel(const float* __restrict__ h0) {
    const int i = blockIdx.x * blockDim.x + threadIdx.x;  // 8192
    const int r = i / HID, k = i % HID;
    ((float*)&g_hbuf[0][(k >> 1) * NENV + r])[k & 1] = h0[i];
}

// ---------------- persistent LSTM over T steps ----------------
__device__ __forceinline__ void grid_bar(unsigned int target) {
    __threadfence();
    __syncthreads();
    if (threadIdx.x == 0) {
        if (atomicAdd(&g_bar_arrive, 1) == (unsigned)gridDim.x - 1) {
            g_bar_arrive = 0;
            __threadfence();
            atomicExch(&g_bar_gen, target);
        } else {
            while ((int)(*(volatile unsigned int*)&g_bar_gen - target) < 0)
                __nanosleep(32);
        }
        __threadfence();
    }
    __syncthreads();
}

__global__ __launch_bounds__(256) void lstm_kernel(
        const float* __restrict__ gt, const float* __restrict__ done,
        const float* __restrict__ c0, const float* __restrict__ wh,
        float* __restrict__ outs) {
    __shared__ __align__(16) ull hs2[128 * NENV];   // packed [k/2][r], 32KB
    __shared__ __align__(16) float whs[8 * HID];    // 8KB
    __shared__ float gsm[8 * NENV];
    __shared__ float cs[2 * NENV];
    __shared__ float ms[NENV];
    __shared__ ull msd[NENV];
    __shared__ unsigned int s_base;

    const int tid = threadIdx.x, blk = blockIdx.x;
    const int w = tid >> 5, lane = tid & 31;
    const int G = (w & 3) * HID + 2 * blk + (w >> 2);  // gate row this warp owns

    for (int k = lane; k < HID; k += 32) whs[w * HID + k] = wh[(size_t)G * HID + k];
    if (tid < 64) {
        const int hcl = tid >> 5, r = tid & 31;
        cs[tid] = c0[r * HID + 2 * blk + hcl];
    }
    if (tid == 0) s_base = g_bar_gen;
    __syncthreads();
    const unsigned int base = s_base;
    const ull* whd = (const ull*)(whs + w * HID);    // 128 packed wh pairs

    for (int t = 0; t < TT; t++) {
        const float giv = gt[(size_t)(t * 1024 + G) * 32 + lane];   // coalesced
        const ull* hsrc = g_hbuf[t & 1];
        if (tid < NENV) {
            const float m = 1.0f - done[t * NENV + tid];
            ms[tid] = m;
            msd[tid] = pk2(m, m);
        }
        __syncthreads();
        // stage masked h into smem (packed pairs, [k/2][r])
        for (int i = tid; i < 128 * NENV; i += 256)
            hs2[i] = fmul2(hsrc[i], msd[i & 31]);
        __syncthreads();

        // gates[r=lane][G] = gi + h[r,:] . wh[G,:]
        ull acc = pk2(giv, 0.f);
#pragma unroll 8
        for (int kp = 0; kp < 128; kp++)
            acc = ffma2(hs2[kp * NENV + lane], whd[kp], acc);
        gsm[w * NENV + lane] = psum(acc);
        __syncthreads();

        ull* hdst = g_hbuf[(t + 1) & 1];
        if (tid < 64) {
            const int hcl = tid >> 5, r = tid & 31;
            const float gi_ = gsm[(hcl * 4 + 0) * NENV + r];
            const float gf_ = gsm[(hcl * 4 + 1) * NENV + r];
            const float gg_ = gsm[(hcl * 4 + 2) * NENV + r];
            const float go_ = gsm[(hcl * 4 + 3) * NENV + r];
            const float iv = 1.f / (1.f + expf(-gi_));
            const float fv = 1.f / (1.f + expf(-gf_));
            const float ov = 1.f / (1.f + expf(-go_));
            const float gv = tanhf(gg_);
            const float c = fv * (cs[tid] * ms[r]) + iv * gv;
            cs[tid] = c;
            const float h = ov * tanhf(c);
            const int hc = 2 * blk + hcl;
            ((float*)&hdst[blk * NENV + r])[hcl] = h;   // packed pair slot
            outs[(size_t)(t * NENV + r) * HID + hc] = h;
        }
        grid_bar(base + t + 1);
    }
}

// ---------------- actor/critic heads ----------------
__global__ void heads_kernel(const float* __restrict__ outs,
                             const float* __restrict__ aw, const float* __restrict__ ab,
                             const float* __restrict__ cw, const float* __restrict__ cb,
                             float* __restrict__ out) {
    __shared__ float hsm[32 * HID];
    const int tid = threadIdx.x, row0 = blockIdx.x * 32;
    for (int i = tid; i < 32 * HID; i += 256) hsm[i] = outs[(size_t)row0 * HID + i];
    __syncthreads();
    for (int o = tid; o < 32 * 19; o += 256) {
        const int r = o / 19, j = o % 19;
        const float* wp = (j < 18) ? (aw + j * HID) : cw;
        const float bias = (j < 18) ? ab[j] : cb[0];
        const float4* h4 = (const float4*)(hsm + r * HID);
        const float4* w4 = (const float4*)wp;
        float acc = 0.f;
#pragma unroll 8
        for (int k = 0; k < HID / 4; k++) {
            const float4 hv = h4[k];
            const float4 wv = __ldg(&w4[k]);
            acc += hv.x*wv.x + hv.y*wv.y + hv.z*wv.z + hv.w*wv.w;
        }
        out[(size_t)(row0 + r) * 19 + j] = acc + bias;
    }
}

// ---------------- launch ----------------
extern "C" void kernel_launch(void* const* d_in, const int* in_sizes, int n_in,
                              void* d_out, int out_size) {
    const float* x    = (const float*)d_in[0];
    const float* done = (const float*)d_in[1];
    const float* h0   = (const float*)d_in[2];
    const float* c0   = (const float*)d_in[3];
    const float* c1w  = (const float*)d_in[4];
    const float* c1b  = (const float*)d_in[5];
    const float* c2w  = (const float*)d_in[6];
    const float* c2b  = (const float*)d_in[7];
    const float* c3w  = (const float*)d_in[8];
    const float* c3b  = (const float*)d_in[9];
    const float* fcw  = (const float*)d_in[10];
    const float* fcb  = (const float*)d_in[11];
    const float* wi   = (const float*)d_in[12];
    const float* wh   = (const float*)d_in[13];
    const float* bi   = (const float*)d_in[14];
    const float* bh   = (const float*)d_in[15];
    const float* aw   = (const float*)d_in[16];
    const float* ab   = (const float*)d_in[17];
    const float* cw   = (const float*)d_in[18];
    const float* cb   = (const float*)d_in[19];
    float* out = (float*)d_out;

    cudaFuncSetAttribute(conv1_kernel, cudaFuncAttributeMaxDynamicSharedMemorySize, 98304);
    cudaFuncSetAttribute(conv2_kernel, cudaFuncAttributeMaxDynamicSharedMemorySize, 163840);
    cudaFuncSetAttribute(conv3_kernel, cudaFuncAttributeMaxDynamicSharedMemorySize, 215040);

    float* out1;  cudaGetSymbolAddress((void**)&out1,  g_out1);
    float* out2;  cudaGetSymbolAddress((void**)&out2,  g_out2);
    float* out3;  cudaGetSymbolAddress((void**)&out3,  g_out3);
    float* feats; cudaGetSymbolAddress((void**)&feats, g_feats);
    float* gi;    cudaGetSymbolAddress((void**)&gi,    g_gi);
    float* gt;    cudaGetSymbolAddress((void**)&gt,    g_gt);
    float* outs;  cudaGetSymbolAddress((void**)&outs,  g_outs);

    conv1_kernel<<<TN, 256, 98304>>>(x, c1w, c1b, out1);
    conv2_kernel<<<TN, 288, 163840>>>(out1, c2w, c2b, out2);
    conv3_kernel<<<TN / 2, 256, 215040>>>(out2, c3w, c3b, out3);
    gemm_nt<<<dim3(512 / 64, TN / 128), 256>>>(out3, fcw, fcb, nullptr, feats, TN, 512, 1024, 1);
    gemm_nt<<<dim3(1024 / 64, TN / 128), 256>>>(feats, wi, bi, bh, gi, TN, 1024, 512, 0);
    gi_transpose<<<dim3(TT, 32), dim3(32, 8)>>>(gi, gt);
    init_h_kernel<<<32, 256>>>(h0);
    lstm_kernel<<<NBLK_LSTM, 256>>>(gt, done, c0, wh, outs);
    heads_kernel<<<TN / 32, 256>>>(outs, aw, ab, cw, cb, out);
}

// round 3
// speedup vs baseline: 1.1226x; 1.0008x over previous
#include <cuda_runtime.h>
#include <math.h>

// ---------------- constants ----------------
#define TN   4096
#define NENV 32
#define TT   128
#define HID  256
#define NBLK_LSTM 128

typedef unsigned long long ull;

// ---------------- packed f32x2 helpers ----------------
__device__ __forceinline__ ull pk2(float lo, float hi) {
    ull r; asm("mov.b64 %0,{%1,%2};" : "=l"(r) : "f"(lo), "f"(hi)); return r;
}
__device__ __forceinline__ void unpk2(ull v, float& lo, float& hi) {
    asm("mov.b64 {%0,%1},%2;" : "=f"(lo), "=f"(hi) : "l"(v));
}
__device__ __forceinline__ ull ffma2(ull a, ull b, ull c) {
    ull d; asm("fma.rn.f32x2 %0,%1,%2,%3;" : "=l"(d) : "l"(a), "l"(b), "l"(c)); return d;
}
__device__ __forceinline__ ull fmul2(ull a, ull b) {
    ull d; asm("mul.rn.f32x2 %0,%1,%2;" : "=l"(d) : "l"(a), "l"(b)); return d;
}
__device__ __forceinline__ float psum(ull v) {
    float lo, hi; unpk2(v, lo, hi); return lo + hi;
}

// ---------------- scratch (device globals; no allocs allowed) ----------------
__device__ float g_out1[TN * 32 * 256];       // conv1 out, rows padded 15->16 (134MB)
__device__ float g_out2[TN * 64 * 6 * 6];     // conv2 out
__device__ float g_out3[TN * 1024];           // conv3 out flattened
__device__ float g_feats[TN * 512];           // fc out
__device__ float g_gi[TN * 1024];             // gate inputs [t*32+r][G]
__device__ float g_gt[TN * 1024];             // gate inputs transposed [t][G][r]
__device__ float g_outs[TN * HID];            // all h_t
__device__ ull   g_hbuf[2][128 * NENV];       // packed h pairs [k/2][r], double buffer
__device__ unsigned int g_bar_arrive = 0;
__device__ unsigned int g_bar_gen = 0;

// ---------------- conv1: (TN,4,64,64) -> (TN,32,15,15pad16), k=8, s=4 ----------
__global__ __launch_bounds__(256) void conv1_kernel(
        const float* __restrict__ x, const float* __restrict__ w,
        const float* __restrict__ b, float* __restrict__ out) {
    extern __shared__ float sm[];
    float* xs = sm;            // 16384 floats
    float* ws = sm + 16384;    // 8192 floats, layout [oc][256]
    const int tid = threadIdx.x;
    const int img = blockIdx.x;

    const float4* xg = (const float4*)(x + (size_t)img * 16384);
    const float inv = 1.0f / 255.0f;
    for (int i = tid; i < 4096; i += 256) {
        float4 v = xg[i];
        v.x *= inv; v.y *= inv; v.z *= inv; v.w *= inv;
        ((float4*)xs)[i] = v;
    }
    for (int i = tid; i < 2048; i += 256)
        ((float4*)ws)[i] = ((const float4*)w)[i];
    __syncthreads();

    if (tid < 225) {
        const int py = tid / 15, px = tid % 15;
        ull acc[32];
#pragma unroll
        for (int oc = 0; oc < 32; oc++) acc[oc] = 0ull;
        const float* xb = xs + py * 256 + px * 4;
#pragma unroll 1
        for (int ik = 0; ik < 32; ik++) {           // ik = ic*8 + ky
            const int ic = ik >> 3, ky = ik & 7;
            const float* xr = xb + ic * 4096 + ky * 64;     // 16B aligned
            const ulonglong2 xa = ((const ulonglong2*)xr)[0];
            const ulonglong2 xc = ((const ulonglong2*)xr)[1];
            const float* wr = ws + ik * 8;          // 32B aligned per oc
#pragma unroll
            for (int oc = 0; oc < 32; oc++) {
                const ulonglong2 w0 = ((const ulonglong2*)(wr + oc * 256))[0];
                const ulonglong2 w1 = ((const ulonglong2*)(wr + oc * 256))[1];
                ull a = acc[oc];
                a = ffma2(xa.x, w0.x, a);
                a = ffma2(xa.y, w0.y, a);
                a = ffma2(xc.x, w1.x, a);
                a = ffma2(xc.y, w1.y, a);
                acc[oc] = a;
            }
        }
        float* op = out + (size_t)img * 8192 + py * 16 + px;
#pragma unroll
        for (int oc = 0; oc < 32; oc++) {
            float v = psum(acc[oc]) + b[oc];
            op[oc * 256] = v > 0.f ? v : 0.f;
        }
    }
}

// ---------------- conv2: (TN,32,16x16pad) -> (TN,64,6,6), k=4, s=2 --------------
__global__ __launch_bounds__(288) void conv2_kernel(
        const float* __restrict__ in, const float* __restrict__ w,
        const float* __restrict__ b, float* __restrict__ out) {
    extern __shared__ float sm[];
    float* xs = sm;            // 8192 floats (padded layout)
    float* ws = sm + 8192;     // 32768 floats, layout [oc][512]
    const int tid = threadIdx.x;
    const int img = blockIdx.x;

    const float4* in4 = (const float4*)(in + (size_t)img * 8192);
    for (int i = tid; i < 2048; i += 288) ((float4*)xs)[i] = in4[i];
    for (int i = tid; i < 8192; i += 288) ((float4*)ws)[i] = ((const float4*)w)[i];
    __syncthreads();

    const int pos = tid % 36, ocg = tid / 36;   // 288 = 8*36 exact
    const int oy = pos / 6, ox = pos % 6;
    ull acc[8];
#pragma unroll
    for (int j = 0; j < 8; j++) acc[j] = 0ull;
    const float* xb = xs + oy * 32 + ox * 2;    // padded: row stride 16, ch stride 256
#pragma unroll 1
    for (int ik = 0; ik < 128; ik++) {          // ik = ic*4 + ky
        const int ic = ik >> 2, ky = ik & 3;
        const float* xr = xb + ic * 256 + ky * 16;  // even offset -> 8B aligned
        const ull x01 = ((const ull*)xr)[0];
        const ull x23 = ((const ull*)xr)[1];
        const float* wr = ws + ocg * 8 * 512 + ik * 4;  // 16B aligned
#pragma unroll
        for (int j = 0; j < 8; j++) {
            const ulonglong2 wv = *(const ulonglong2*)(wr + j * 512);
            ull a = acc[j];
            a = ffma2(x01, wv.x, a);
            a = ffma2(x23, wv.y, a);
            acc[j] = a;
        }
    }
    float* op = out + (size_t)img * 2304 + pos;
#pragma unroll
    for (int j = 0; j < 8; j++) {
        const int oc = ocg * 8 + j;
        float v = psum(acc[j]) + b[oc];
        op[oc * 36] = v > 0.f ? v : 0.f;
    }
}

// ---------------- conv3: (TN,64,6,6) -> (TN,64,4,4), k=3, s=1 ; 2 imgs/block ----
__global__ __launch_bounds__(256) void conv3_kernel(
        const float* __restrict__ in, const float* __restrict__ w,
        const float* __restrict__ b, float* __restrict__ out) {
    extern __shared__ float sm[];
    float* xs = sm;            // 2*2304
    float* ws = sm + 4608;     // 64*768 floats, layout [oc][ic*12 + ky*4 + kx], kx pad=0
    const int tid = threadIdx.x;
    const int blk = blockIdx.x;

    for (int i = tid; i < 4608; i += 256) xs[i] = in[(size_t)blk * 4608 + i];
    // zero pad slots
    for (int i = tid; i < 64 * 64 * 3; i += 256) {
        const int oc = i / 192, rem = i % 192;     // rem = ic*3+ky
        const int ic = rem / 3, ky = rem % 3;
        ws[oc * 768 + ic * 12 + ky * 4 + 3] = 0.f;
    }
    for (int i = tid; i < 64 * 576; i += 256) {
        const int oc = i / 576, rem = i % 576;
        const int ic = rem / 9, kk = rem % 9;
        const int ky = kk / 3, kx = kk % 3;
        ws[oc * 768 + ic * 12 + ky * 4 + kx] = w[i];
    }
    __syncthreads();

    const int half = tid >> 7, t = tid & 127;
    const int pos = t & 15, ocg = t >> 4;
    const int oy = pos >> 2, ox = pos & 3;
    const int img = blk * 2 + half;
    ull acc[8];
#pragma unroll
    for (int j = 0; j < 8; j++) acc[j] = 0ull;
    const float* xb = xs + half * 2304 + oy * 6 + ox;
#pragma unroll 1
    for (int ic = 0; ic < 64; ic++) {
        const float* xc = xb + ic * 36;
        const float* wc = ws + ocg * 8 * 768 + ic * 12;
#pragma unroll
        for (int ky = 0; ky < 3; ky++) {
            const float x0 = xc[ky*6+0], x1 = xc[ky*6+1], x2 = xc[ky*6+2];
            const ull xp01 = pk2(x0, x1);
            const ull xp2  = pk2(x2, 0.f);
            const float* wr = wc + ky * 4;          // 16B aligned
#pragma unroll
            for (int j = 0; j < 8; j++) {
                const ulonglong2 wv = *(const ulonglong2*)(wr + j * 768);
                ull a = acc[j];
                a = ffma2(xp01, wv.x, a);
                a = ffma2(xp2,  wv.y, a);
                acc[j] = a;
            }
        }
    }
    float* op = out + (size_t)img * 1024 + pos;
#pragma unroll
    for (int j = 0; j < 8; j++) {
        const int oc = ocg * 8 + j;
        float v = psum(acc[j]) + b[oc];
        op[oc * 16] = v > 0.f ? v : 0.f;   // flatten = c*16 + y*4 + x
    }
}

// ---------------- tiled NT GEMM (FFMA2): C = act(A[MxK] B[NxK]^T + b1 + b2) -----
// 128x64 tile, 256 threads, thread micro-tile = 8 rows (4 packed pairs) x 4 cols
__global__ __launch_bounds__(256) void gemm_nt(
        const float* __restrict__ A, const float* __restrict__ B,
        const float* __restrict__ bias1, const float* __restrict__ bias2,
        float* __restrict__ C, int M, int N, int K, int do_relu) {
    __shared__ __align__(16) float As[16][128];   // [k][m]
    __shared__ __align__(16) ull   Bs[16][64];    // [k][n] pre-duplicated pairs
    const int tid = threadIdx.x;
    const int m0 = blockIdx.y * 128, n0 = blockIdx.x * 64;
    const int arow = tid >> 1, ahalf = tid & 1;
    const int brow = tid >> 2, bq = tid & 3;
    const int ty = tid >> 4, tx = tid & 15;
    const float* Ap = A + (size_t)(m0 + arow) * K + ahalf * 8;
    const float* Bp = B + (size_t)(n0 + brow) * K + bq * 4;

    ull acc[4][4];
#pragma unroll
    for (int i = 0; i < 4; i++)
#pragma unroll
        for (int j = 0; j < 4; j++) acc[i][j] = 0ull;

    for (int k0 = 0; k0 < K; k0 += 16) {
        const float4 a0 = *(const float4*)(Ap + k0);
        const float4 a1 = *(const float4*)(Ap + k0 + 4);
        const float4 bv = *(const float4*)(Bp + k0);
        __syncthreads();
        As[ahalf*8+0][arow] = a0.x; As[ahalf*8+1][arow] = a0.y;
        As[ahalf*8+2][arow] = a0.z; As[ahalf*8+3][arow] = a0.w;
        As[ahalf*8+4][arow] = a1.x; As[ahalf*8+5][arow] = a1.y;
        As[ahalf*8+6][arow] = a1.z; As[ahalf*8+7][arow] = a1.w;
        Bs[bq*4+0][brow] = pk2(bv.x, bv.x);
        Bs[bq*4+1][brow] = pk2(bv.y, bv.y);
        Bs[bq*4+2][brow] = pk2(bv.z, bv.z);
        Bs[bq*4+3][brow] = pk2(bv.w, bv.w);
        __syncthreads();
#pragma unroll
        for (int kk = 0; kk < 16; kk++) {
            const ulonglong2 ap0 = ((const ulonglong2*)&As[kk][0])[ty*2];
            const ulonglong2 ap1 = ((const ulonglong2*)&As[kk][0])[ty*2+1];
            const ulonglong2 bp0 = ((const ulonglong2*)&Bs[kk][0])[tx*2];
            const ulonglong2 bp1 = ((const ulonglong2*)&Bs[kk][0])[tx*2+1];
            const ull ar[4] = {ap0.x, ap0.y, ap1.x, ap1.y};
            const ull br[4] = {bp0.x, bp0.y, bp1.x, bp1.y};
#pragma unroll
            for (int i = 0; i < 4; i++)
#pragma unroll
                for (int j = 0; j < 4; j++)
                    acc[i][j] = ffma2(ar[i], br[j], acc[i][j]);
        }
    }

    const int n = n0 + tx * 4;
    float bb[4];
#pragma unroll
    for (int j = 0; j < 4; j++) {
        float v = bias1 ? bias1[n + j] : 0.f;
        if (bias2) v += bias2[n + j];
        bb[j] = v;
    }
    const int mrow = m0 + ty * 8;
#pragma unroll
    for (int i = 0; i < 4; i++) {
        float4 v0, v1;
        float* p0 = &v0.x; float* p1 = &v1.x;
#pragma unroll
        for (int j = 0; j < 4; j++) {
            float lo, hi; unpk2(acc[i][j], lo, hi);
            float u0 = lo + bb[j], u1 = hi + bb[j];
            if (do_relu) { u0 = u0 > 0.f ? u0 : 0.f; u1 = u1 > 0.f ? u1 : 0.f; }
            p0[j] = u0; p1[j] = u1;
        }
        *(float4*)&C[(size_t)(mrow + 2*i + 0) * N + n] = v0;
        *(float4*)&C[(size_t)(mrow + 2*i + 1) * N + n] = v1;
    }
}

// ---------------- gi transpose: [t*32+r][G] -> [t][G][r] ----------------
__global__ void gi_transpose(const float* __restrict__ gi, float* __restrict__ gt) {
    __shared__ float tile[32][33];
    const int t = blockIdx.x, gb = blockIdx.y;
    const int tx = threadIdx.x, ty = threadIdx.y;      // (32, 8)
    for (int rr = ty; rr < 32; rr += 8)
        tile[rr][tx] = gi[(size_t)(t * 32 + rr) * 1024 + gb * 32 + tx];
    __syncthreads();
    for (int gg = ty; gg < 32; gg += 8)
        gt[(size_t)(t * 1024 + gb * 32 + gg) * 32 + tx] = tile[tx][gg];
}

// ---------------- h0 into packed double buffer ----------------
__global__ void init_h_kernel(const float* __restrict__ h0) {
    const int i = blockIdx.x * blockDim.x + threadIdx.x;  // 8192
    const int r = i / HID, k = i % HID;
    ((float*)&g_hbuf[0][(k >> 1) * NENV + r])[k & 1] = h0[i];
}

// ---------------- persistent LSTM over T steps ----------------
__device__ __forceinline__ void grid_bar(unsigned int target) {
    __threadfence();
    __syncthreads();
    if (threadIdx.x == 0) {
        if (atomicAdd(&g_bar_arrive, 1) == (unsigned)gridDim.x - 1) {
            g_bar_arrive = 0;
            __threadfence();
            atomicExch(&g_bar_gen, target);
        } else {
            while ((int)(*(volatile unsigned int*)&g_bar_gen - target) < 0)
                __nanosleep(32);
        }
        __threadfence();
    }
    __syncthreads();
}

__global__ __launch_bounds__(256) void lstm_kernel(
        const float* __restrict__ gt, const float* __restrict__ done,
        const float* __restrict__ c0, const float* __restrict__ wh,
        float* __restrict__ outs) {
    __shared__ __align__(16) ull hs2[128 * NENV];   // packed [k/2][r], 32KB
    __shared__ __align__(16) float whs[8 * HID];    // 8KB
    __shared__ float gsm[8 * NENV];
    __shared__ float cs[2 * NENV];
    __shared__ float ms[NENV];
    __shared__ ull msd[NENV];
    __shared__ unsigned int s_base;

    const int tid = threadIdx.x, blk = blockIdx.x;
    const int w = tid >> 5, lane = tid & 31;
    const int G = (w & 3) * HID + 2 * blk + (w >> 2);  // gate row this warp owns

    for (int k = lane; k < HID; k += 32) whs[w * HID + k] = wh[(size_t)G * HID + k];
    if (tid < 64) {
        const int hcl = tid >> 5, r = tid & 31;
        cs[tid] = c0[r * HID + 2 * blk + hcl];
    }
    if (tid == 0) s_base = g_bar_gen;
    __syncthreads();
    const unsigned int base = s_base;
    const ull* whd = (const ull*)(whs + w * HID);    // 128 packed wh pairs

    for (int t = 0; t < TT; t++) {
        const float giv = gt[(size_t)(t * 1024 + G) * 32 + lane];   // coalesced
        const ull* hsrc = g_hbuf[t & 1];
        if (tid < NENV) {
            const float m = 1.0f - done[t * NENV + tid];
            ms[tid] = m;
            msd[tid] = pk2(m, m);
        }
        __syncthreads();
        // stage masked h into smem (packed pairs, [k/2][r])
        for (int i = tid; i < 128 * NENV; i += 256)
            hs2[i] = fmul2(hsrc[i], msd[i & 31]);
        __syncthreads();

        // gates[r=lane][G] = gi + h[r,:] . wh[G,:]
        ull acc = pk2(giv, 0.f);
#pragma unroll 8
        for (int kp = 0; kp < 128; kp++)
            acc = ffma2(hs2[kp * NENV + lane], whd[kp], acc);
        gsm[w * NENV + lane] = psum(acc);
        __syncthreads();

        ull* hdst = g_hbuf[(t + 1) & 1];
        if (tid < 64) {
            const int hcl = tid >> 5, r = tid & 31;
            const float gi_ = gsm[(hcl * 4 + 0) * NENV + r];
            const float gf_ = gsm[(hcl * 4 + 1) * NENV + r];
            const float gg_ = gsm[(hcl * 4 + 2) * NENV + r];
            const float go_ = gsm[(hcl * 4 + 3) * NENV + r];
            const float iv = 1.f / (1.f + expf(-gi_));
            const float fv = 1.f / (1.f + expf(-gf_));
            const float ov = 1.f / (1.f + expf(-go_));
            const float gv = tanhf(gg_);
            const float c = fv * (cs[tid] * ms[r]) + iv * gv;
            cs[tid] = c;
            const float h = ov * tanhf(c);
            const int hc = 2 * blk + hcl;
            ((float*)&hdst[blk * NENV + r])[hcl] = h;   // packed pair slot
            outs[(size_t)(t * NENV + r) * HID + hc] = h;
        }
        grid_bar(base + t + 1);
    }
}

// ---------------- actor/critic heads ----------------
__global__ void heads_kernel(const float* __restrict__ outs,
                             const float* __restrict__ aw, const float* __restrict__ ab,
                             const float* __restrict__ cw, const float* __restrict__ cb,
                             float* __restrict__ out) {
    __shared__ float hsm[32 * HID];
    const int tid = threadIdx.x, row0 = blockIdx.x * 32;
    for (int i = tid; i < 32 * HID; i += 256) hsm[i] = outs[(size_t)row0 * HID + i];
    __syncthreads();
    for (int o = tid; o < 32 * 19; o += 256) {
        const int r = o / 19, j = o % 19;
        const float* wp = (j < 18) ? (aw + j * HID) : cw;
        const float bias = (j < 18) ? ab[j] : cb[0];
        const float4* h4 = (const float4*)(hsm + r * HID);
        const float4* w4 = (const float4*)wp;
        float acc = 0.f;
#pragma unroll 8
        for (int k = 0; k < HID / 4; k++) {
            const float4 hv = h4[k];
            const float4 wv = __ldg(&w4[k]);
            acc += hv.x*wv.x + hv.y*wv.y + hv.z*wv.z + hv.w*wv.w;
        }
        out[(size_t)(row0 + r) * 19 + j] = acc + bias;
    }
}

// ---------------- launch ----------------
extern "C" void kernel_launch(void* const* d_in, const int* in_sizes, int n_in,
                              void* d_out, int out_size) {
    const float* x    = (const float*)d_in[0];
    const float* done = (const float*)d_in[1];
    const float* h0   = (const float*)d_in[2];
    const float* c0   = (const float*)d_in[3];
    const float* c1w  = (const float*)d_in[4];
    const float* c1b  = (const float*)d_in[5];
    const float* c2w  = (const float*)d_in[6];
    const float* c2b  = (const float*)d_in[7];
    const float* c3w  = (const float*)d_in[8];
    const float* c3b  = (const float*)d_in[9];
    const float* fcw  = (const float*)d_in[10];
    const float* fcb  = (const float*)d_in[11];
    const float* wi   = (const float*)d_in[12];
    const float* wh   = (const float*)d_in[13];
    const float* bi   = (const float*)d_in[14];
    const float* bh   = (const float*)d_in[15];
    const float* aw   = (const float*)d_in[16];
    const float* ab   = (const float*)d_in[17];
    const float* cw   = (const float*)d_in[18];
    const float* cb   = (const float*)d_in[19];
    float* out = (float*)d_out;

    cudaFuncSetAttribute(conv1_kernel, cudaFuncAttributeMaxDynamicSharedMemorySize, 98304);
    cudaFuncSetAttribute(conv2_kernel, cudaFuncAttributeMaxDynamicSharedMemorySize, 163840);
    cudaFuncSetAttribute(conv3_kernel, cudaFuncAttributeMaxDynamicSharedMemorySize, 215040);

    float* out1;  cudaGetSymbolAddress((void**)&out1,  g_out1);
    float* out2;  cudaGetSymbolAddress((void**)&out2,  g_out2);
    float* out3;  cudaGetSymbolAddress((void**)&out3,  g_out3);
    float* feats; cudaGetSymbolAddress((void**)&feats, g_feats);
    float* gi;    cudaGetSymbolAddress((void**)&gi,    g_gi);
    float* gt;    cudaGetSymbolAddress((void**)&gt,    g_gt);
    float* outs;  cudaGetSymbolAddress((void**)&outs,  g_outs);

    conv1_kernel<<<TN, 256, 98304>>>(x, c1w, c1b, out1);
    conv2_kernel<<<TN, 288, 163840>>>(out1, c2w, c2b, out2);
    conv3_kernel<<<TN / 2, 256, 215040>>>(out2, c3w, c3b, out3);
    gemm_nt<<<dim3(512 / 64, TN / 128), 256>>>(out3, fcw, fcb, nullptr, feats, TN, 512, 1024, 1);
    gemm_nt<<<dim3(1024 / 64, TN / 128), 256>>>(feats, wi, bi, bh, gi, TN, 1024, 512, 0);
    gi_transpose<<<dim3(TT, 32), dim3(32, 8)>>>(gi, gt);
    init_h_kernel<<<32, 256>>>(h0);
    lstm_kernel<<<NBLK_LSTM, 256>>>(gt, done, c0, wh, outs);
    heads_kernel<<<TN / 32, 256>>>(outs, aw, ab, cw, cb, out);
}

// round 4
// speedup vs baseline: 1.3833x; 1.2322x over previous
#include <cuda_runtime.h>
#include <math.h>

#define TN   4096
#define NENV 32
#define TT   128
#define HID  256
#define NBLK_LSTM 128

typedef unsigned long long ull;

__device__ __forceinline__ ull pk2(float lo, float hi) {
    ull r; asm("mov.b64 %0,{%1,%2};" : "=l"(r) : "f"(lo), "f"(hi)); return r;
}
__device__ __forceinline__ void unpk2(ull v, float& lo, float& hi) {
    asm("mov.b64 {%0,%1},%2;" : "=f"(lo), "=f"(hi) : "l"(v));
}
__device__ __forceinline__ ull ffma2(ull a, ull b, ull c) {
    ull d; asm("fma.rn.f32x2 %0,%1,%2,%3;" : "=l"(d) : "l"(a), "l"(b), "l"(c)); return d;
}
__device__ __forceinline__ float psum(ull v) {
    float lo, hi; unpk2(v, lo, hi); return lo + hi;
}

// ---------------- scratch ----------------
__device__ float g_out1[TN * 32 * 256];
__device__ float g_out2[TN * 64 * 36];
__device__ float g_out3[TN * 1024];
__device__ float g_feats[TN * 512];
__device__ float g_gi[TN * 1024];
__device__ float g_gt[TN * 1024];
__device__ float g_outs[TN * HID];
__device__ ull   g_hbuf[2][128 * NENV];
__device__ float g_w3p[64 * 768];
__device__ int   g_flags[NBLK_LSTM];

// ---------------- conv1: (TN,4,64,64)->(TN,32,15,15pad16), k8 s4, 2 px/thread ----
__global__ __launch_bounds__(256, 2) void conv1_kernel(
        const float* __restrict__ x, const float* __restrict__ w,
        const float* __restrict__ b, float* __restrict__ out) {
    extern __shared__ float sm[];
    float* xs = sm;            // 16384
    float* ws = sm + 16384;    // 8192 [oc][256]
    const int tid = threadIdx.x, img = blockIdx.x;
    const float4* xg = (const float4*)(x + (size_t)img * 16384);
    const float inv = 1.0f / 255.0f;
    for (int i = tid; i < 4096; i += 256) {
        float4 v = xg[i];
        v.x *= inv; v.y *= inv; v.z *= inv; v.w *= inv;
        ((float4*)xs)[i] = v;
    }
    for (int i = tid; i < 2048; i += 256)
        ((float4*)ws)[i] = ((const float4*)w)[i];
    __syncthreads();

    const int och = tid >> 7, u = tid & 127;
    if (u > 112) return;
    const int p0 = 2 * u;
    const bool p1v = (p0 + 1) < 225;
    const int p1 = p1v ? (p0 + 1) : p0;
    const int py0 = p0 / 15, px0 = p0 % 15;
    const int py1 = p1 / 15, px1 = p1 % 15;

    ull a0[16], a1[16];
#pragma unroll
    for (int j = 0; j < 16; j++) { a0[j] = 0ull; a1[j] = 0ull; }
    const float* xb0 = xs + py0 * 256 + px0 * 4;
    const float* xb1 = xs + py1 * 256 + px1 * 4;
#pragma unroll 1
    for (int ik = 0; ik < 32; ik++) {
        const int ic = ik >> 3, ky = ik & 7;
        const float* xr0 = xb0 + ic * 4096 + ky * 64;
        const float* xr1 = xb1 + ic * 4096 + ky * 64;
        const ulonglong2 xa0 = ((const ulonglong2*)xr0)[0];
        const ulonglong2 xc0 = ((const ulonglong2*)xr0)[1];
        const ulonglong2 xa1 = ((const ulonglong2*)xr1)[0];
        const ulonglong2 xc1 = ((const ulonglong2*)xr1)[1];
        const float* wr = ws + (och * 16) * 256 + ik * 8;
#pragma unroll
        for (int j = 0; j < 16; j++) {
            const ulonglong2 w0 = ((const ulonglong2*)(wr + j * 256))[0];
            const ulonglong2 w1 = ((const ulonglong2*)(wr + j * 256))[1];
            ull s0 = a0[j];
            s0 = ffma2(xa0.x, w0.x, s0); s0 = ffma2(xa0.y, w0.y, s0);
            s0 = ffma2(xc0.x, w1.x, s0); s0 = ffma2(xc0.y, w1.y, s0);
            a0[j] = s0;
            ull s1 = a1[j];
            s1 = ffma2(xa1.x, w0.x, s1); s1 = ffma2(xa1.y, w0.y, s1);
            s1 = ffma2(xc1.x, w1.x, s1); s1 = ffma2(xc1.y, w1.y, s1);
            a1[j] = s1;
        }
    }
    float* base = out + (size_t)img * 8192;
#pragma unroll
    for (int j = 0; j < 16; j++) {
        const int oc = och * 16 + j;
        const float bias = b[oc];
        float v0 = psum(a0[j]) + bias;
        base[oc * 256 + py0 * 16 + px0] = v0 > 0.f ? v0 : 0.f;
        if (p1v) {
            float v1 = psum(a1[j]) + bias;
            base[oc * 256 + py1 * 16 + px1] = v1 > 0.f ? v1 : 0.f;
        }
    }
}

// ---------------- conv2: k4 s2, weights via uniform __ldg, 2 pos/thread ----------
__global__ __launch_bounds__(144) void conv2_kernel(
        const float* __restrict__ in, const float* __restrict__ w,
        const float* __restrict__ b, float* __restrict__ out) {
    __shared__ __align__(16) float xs[8192];
    const int tid = threadIdx.x, img = blockIdx.x;
    const float4* in4 = (const float4*)(in + (size_t)img * 8192);
    for (int i = tid; i < 2048; i += 144) ((float4*)xs)[i] = in4[i];
    __syncthreads();

    const int u = tid % 18, ocg = tid / 18;
    const int p0 = 2 * u;
    const int oy = p0 / 6, ox0 = p0 % 6;
    ull a0[8], a1[8];
#pragma unroll
    for (int j = 0; j < 8; j++) { a0[j] = 0ull; a1[j] = 0ull; }
    const float* xb = xs + oy * 32 + ox0 * 2;
#pragma unroll 2
    for (int ik = 0; ik < 128; ik++) {
        const int ic = ik >> 2, ky = ik & 3;
        const float* xr = xb + ic * 256 + ky * 16;
        const ull x01a = ((const ull*)xr)[0];
        const ull x23a = ((const ull*)xr)[1];
        const ull x01b = ((const ull*)(xr + 2))[0];
        const ull x23b = ((const ull*)(xr + 2))[1];
        const ulonglong2* wp = (const ulonglong2*)(w + (size_t)(ocg * 8) * 512 + ik * 4);
#pragma unroll
        for (int j = 0; j < 8; j++) {
            const ulonglong2 wv = __ldg(wp + j * 128);
            a0[j] = ffma2(x01a, wv.x, a0[j]);
            a0[j] = ffma2(x23a, wv.y, a0[j]);
            a1[j] = ffma2(x01b, wv.x, a1[j]);
            a1[j] = ffma2(x23b, wv.y, a1[j]);
        }
    }
    float* op = out + (size_t)img * 2304;
#pragma unroll
    for (int j = 0; j < 8; j++) {
        const int oc = ocg * 8 + j;
        const float bias = b[oc];
        float v0 = psum(a0[j]) + bias;
        float v1 = psum(a1[j]) + bias;
        op[oc * 36 + p0]     = v0 > 0.f ? v0 : 0.f;
        op[oc * 36 + p0 + 1] = v1 > 0.f ? v1 : 0.f;
    }
}

// ---------------- conv3 weight prep: pad kx 3->4 ----------------
__global__ void prep_w3(const float* __restrict__ w) {
    const int i = blockIdx.x * 256 + threadIdx.x;
    if (i >= 64 * 768) return;
    const int oc = i / 768, r = i % 768;
    const int ic = r / 12, q = r % 12;
    const int ky = q >> 2, kx = q & 3;
    g_w3p[i] = (kx < 3) ? w[oc * 576 + ic * 9 + ky * 3 + kx] : 0.f;
}

// ---------------- conv3: k3 s1, 4 imgs/block, uniform __ldg weights --------------
__global__ __launch_bounds__(256) void conv3_kernel(
        const float* __restrict__ in, const float* __restrict__ w3p,
        const float* __restrict__ b, float* __restrict__ out) {
    __shared__ __align__(16) float xs[4 * 2304];
    const int tid = threadIdx.x, blk = blockIdx.x;
    const float4* in4 = (const float4*)(in + (size_t)blk * 9216);
    for (int i = tid; i < 2304; i += 256) ((float4*)xs)[i] = in4[i];
    __syncthreads();

    const int img_l = tid >> 6, t = tid & 63;
    const int ocg = t >> 3, u = t & 7;
    const int oy = u >> 1, ox0 = (u & 1) * 2;
    const int p0 = oy * 4 + ox0;
    ull a0[8], a1[8];
#pragma unroll
    for (int j = 0; j < 8; j++) { a0[j] = 0ull; a1[j] = 0ull; }
    const float* xb = xs + img_l * 2304 + oy * 6 + ox0;
#pragma unroll 1
    for (int ic = 0; ic < 64; ic++) {
        const float* xc = xb + ic * 36;
#pragma unroll
        for (int ky = 0; ky < 3; ky++) {
            const float* row = xc + ky * 6;
            const ull xab = ((const ull*)row)[0];
            const ull xcd = ((const ull*)row)[1];
            float x0, x1, x2, x3;
            unpk2(xab, x0, x1); unpk2(xcd, x2, x3);
            const ull q0b = pk2(x2, 0.f);
            const ull q1a = pk2(x1, x2);
            const ull q1b = pk2(x3, 0.f);
            const ulonglong2* wp = (const ulonglong2*)(w3p + (size_t)(ocg * 8) * 768 + ic * 12 + ky * 4);
#pragma unroll
            for (int j = 0; j < 8; j++) {
                const ulonglong2 wv = __ldg(wp + j * 192);
                a0[j] = ffma2(xab, wv.x, a0[j]);
                a0[j] = ffma2(q0b, wv.y, a0[j]);
                a1[j] = ffma2(q1a, wv.x, a1[j]);
                a1[j] = ffma2(q1b, wv.y, a1[j]);
            }
        }
    }
    const int img = blk * 4 + img_l;
    float* op = out + (size_t)img * 1024;
#pragma unroll
    for (int j = 0; j < 8; j++) {
        const int oc = ocg * 8 + j;
        const float bias = b[oc];
        float v0 = psum(a0[j]) + bias;
        float v1 = psum(a1[j]) + bias;
        op[oc * 16 + p0]     = v0 > 0.f ? v0 : 0.f;
        op[oc * 16 + p0 + 1] = v1 > 0.f ? v1 : 0.f;
    }
}

// ---------------- GEMM NT: 128x128 tile, 256 thr, 8x8 micro, A dup'd in smem -----
__global__ __launch_bounds__(256, 2) void gemm_nt(
        const float* __restrict__ A, const float* __restrict__ B,
        const float* __restrict__ bias1, const float* __restrict__ bias2,
        float* __restrict__ C, int M, int N, int K, int do_relu) {
    __shared__ __align__(16) ull   As[2][16][128];   // dup pairs of A[m]
    __shared__ __align__(16) float Bs[2][16][128];
    const int tid = threadIdx.x;
    const int m0 = blockIdx.y * 128, n0 = blockIdx.x * 128;
    const int row = tid >> 1, half = tid & 1;
    const int ty = tid >> 4, tx = tid & 15;
    const float* Ap = A + (size_t)(m0 + row) * K + half * 8;
    const float* Bp = B + (size_t)(n0 + row) * K + half * 8;

    ull acc[8][4];
#pragma unroll
    for (int i = 0; i < 8; i++)
#pragma unroll
        for (int j = 0; j < 4; j++) acc[i][j] = 0ull;

    // prologue stage k-block 0
    {
        const float4 a0 = *(const float4*)(Ap), a1 = *(const float4*)(Ap + 4);
        const float4 b0 = *(const float4*)(Bp), b1 = *(const float4*)(Bp + 4);
        const float af[8] = {a0.x,a0.y,a0.z,a0.w,a1.x,a1.y,a1.z,a1.w};
        const float bf[8] = {b0.x,b0.y,b0.z,b0.w,b1.x,b1.y,b1.z,b1.w};
#pragma unroll
        for (int e = 0; e < 8; e++) {
            As[0][half * 8 + e][row] = pk2(af[e], af[e]);
            Bs[0][half * 8 + e][row] = bf[e];
        }
    }
    __syncthreads();

    int buf = 0;
    for (int k0 = 0; k0 < K; k0 += 16) {
        const bool more = (k0 + 16) < K;
        float4 a0, a1, b0, b1;
        if (more) {
            a0 = *(const float4*)(Ap + k0 + 16); a1 = *(const float4*)(Ap + k0 + 20);
            b0 = *(const float4*)(Bp + k0 + 16); b1 = *(const float4*)(Bp + k0 + 20);
        }
#pragma unroll
        for (int kk = 0; kk < 16; kk++) {
            ull ad[8];
#pragma unroll
            for (int q = 0; q < 4; q++) {
                const ulonglong2 av = *(const ulonglong2*)&As[buf][kk][ty * 8 + q * 2];
                ad[q * 2] = av.x; ad[q * 2 + 1] = av.y;
            }
            const ulonglong2 bp0 = ((const ulonglong2*)&Bs[buf][kk][0])[tx * 2];
            const ulonglong2 bp1 = ((const ulonglong2*)&Bs[buf][kk][0])[tx * 2 + 1];
            const ull bd[4] = {bp0.x, bp0.y, bp1.x, bp1.y};
#pragma unroll
            for (int i = 0; i < 8; i++)
#pragma unroll
                for (int j = 0; j < 4; j++)
                    acc[i][j] = ffma2(ad[i], bd[j], acc[i][j]);
        }
        if (more) {
            const int nb = buf ^ 1;
            const float af[8] = {a0.x,a0.y,a0.z,a0.w,a1.x,a1.y,a1.z,a1.w};
            const float bf[8] = {b0.x,b0.y,b0.z,b0.w,b1.x,b1.y,b1.z,b1.w};
#pragma unroll
            for (int e = 0; e < 8; e++) {
                As[nb][half * 8 + e][row] = pk2(af[e], af[e]);
                Bs[nb][half * 8 + e][row] = bf[e];
            }
        }
        __syncthreads();
        buf ^= 1;
    }

    const int n = n0 + tx * 8;
    float bb[8];
#pragma unroll
    for (int j = 0; j < 8; j++) {
        float v = bias1 ? bias1[n + j] : 0.f;
        if (bias2) v += bias2[n + j];
        bb[j] = v;
    }
#pragma unroll
    for (int i = 0; i < 8; i++) {
        float r[8];
#pragma unroll
        for (int j = 0; j < 4; j++) {
            float lo, hi; unpk2(acc[i][j], lo, hi);
            r[2 * j] = lo + bb[2 * j]; r[2 * j + 1] = hi + bb[2 * j + 1];
            if (do_relu) {
                r[2 * j] = r[2 * j] > 0.f ? r[2 * j] : 0.f;
                r[2 * j + 1] = r[2 * j + 1] > 0.f ? r[2 * j + 1] : 0.f;
            }
        }
        float* cp = &C[(size_t)(m0 + ty * 8 + i) * N + n];
        *(float4*)(cp)     = make_float4(r[0], r[1], r[2], r[3]);
        *(float4*)(cp + 4) = make_float4(r[4], r[5], r[6], r[7]);
    }
}

// ---------------- gi transpose: [t*32+r][G] -> [t][G][r] ----------------
__global__ void gi_transpose(const float* __restrict__ gi, float* __restrict__ gt) {
    __shared__ float tile[32][33];
    const int t = blockIdx.x, gb = blockIdx.y;
    const int tx = threadIdx.x, ty = threadIdx.y;
    for (int rr = ty; rr < 32; rr += 8)
        tile[rr][tx] = gi[(size_t)(t * 32 + rr) * 1024 + gb * 32 + tx];
    __syncthreads();
    for (int gg = ty; gg < 32; gg += 8)
        gt[(size_t)(t * 1024 + gb * 32 + gg) * 32 + tx] = tile[tx][gg];
}

__global__ void init_h_kernel(const float* __restrict__ h0) {
    const int i = blockIdx.x * blockDim.x + threadIdx.x;
    const int r = i / HID, k = i % HID;
    ((float*)&g_hbuf[0][(k >> 1) * NENV + r])[k & 1] = h0[i];
}

// ---------------- persistent LSTM with flag-array barrier ----------------
__global__ __launch_bounds__(256) void lstm_kernel(
        const float* __restrict__ gt, const float* __restrict__ done,
        const float* __restrict__ c0, const float* __restrict__ wh,
        float* __restrict__ outs) {
    __shared__ __align__(16) ull hs2[128 * NENV];
    __shared__ __align__(16) float whs[8 * HID];
    __shared__ float gsm[8 * NENV];
    __shared__ float cs[2 * NENV];
    __shared__ float ms[NENV];
    __shared__ int s_base;

    const int tid = threadIdx.x, blk = blockIdx.x;
    const int w = tid >> 5, lane = tid & 31;
    const int G = (w & 3) * HID + 2 * blk + (w >> 2);

    for (int k = lane; k < HID; k += 32) whs[w * HID + k] = wh[(size_t)G * HID + k];
    if (tid < 64) {
        const int hcl = tid >> 5, r = tid & 31;
        cs[tid] = c0[r * HID + 2 * blk + hcl];
    }
    if (tid == 0) s_base = *(volatile int*)&g_flags[blk];
    __syncthreads();
    const int base = s_base;
    const ull* whd = (const ull*)(whs + w * HID);

    for (int t = 0; t < TT; t++) {
        const float giv = __ldg(&gt[(size_t)(t * 1024 + G) * 32 + lane]);
        const float4* hsrc = (const float4*)g_hbuf[t & 1];
        if (tid < NENV) ms[tid] = 1.0f - done[t * NENV + tid];
#pragma unroll
        for (int i = 0; i < 8; i++)
            ((float4*)hs2)[tid + i * 256] = __ldcg(&hsrc[tid + i * 256]);
        __syncthreads();

        ull acc = 0ull;
#pragma unroll 8
        for (int kp = 0; kp < 128; kp++)
            acc = ffma2(hs2[kp * NENV + lane], whd[kp], acc);
        gsm[w * NENV + lane] = giv + ms[lane] * psum(acc);
        __syncthreads();

        ull* hdst = g_hbuf[(t + 1) & 1];
        if (tid < 64) {
            const int hcl = tid >> 5, r = tid & 31;
            const float gi_ = gsm[(hcl * 4 + 0) * NENV + r];
            const float gf_ = gsm[(hcl * 4 + 1) * NENV + r];
            const float gg_ = gsm[(hcl * 4 + 2) * NENV + r];
            const float go_ = gsm[(hcl * 4 + 3) * NENV + r];
            const float iv = 1.f / (1.f + expf(-gi_));
            const float fv = 1.f / (1.f + expf(-gf_));
            const float ov = 1.f / (1.f + expf(-go_));
            const float gv = tanhf(gg_);
            const float c = fv * (cs[tid] * ms[r]) + iv * gv;
            cs[tid] = c;
            const float h = ov * tanhf(c);
            const int hc = 2 * blk + hcl;
            ((float*)&hdst[blk * NENV + r])[hcl] = h;
            outs[(size_t)(t * NENV + r) * HID + hc] = h;
        }
        __threadfence();
        __syncthreads();
        const int tgt = base + t + 1;
        if (tid == 0) *(volatile int*)&g_flags[blk] = tgt;
        if (w == 0) {
#pragma unroll
            for (int q = 0; q < 4; q++)
                while (*(volatile int*)&g_flags[lane + q * 32] - tgt < 0)
                    __nanosleep(32);
        }
        __syncthreads();
    }
}

// ---------------- actor/critic heads ----------------
__global__ void heads_kernel(const float* __restrict__ outs,
                             const float* __restrict__ aw, const float* __restrict__ ab,
                             const float* __restrict__ cw, const float* __restrict__ cb,
                             float* __restrict__ out) {
    __shared__ float hsm[32 * HID];
    const int tid = threadIdx.x, row0 = blockIdx.x * 32;
    for (int i = tid; i < 32 * HID; i += 256) hsm[i] = outs[(size_t)row0 * HID + i];
    __syncthreads();
    for (int o = tid; o < 32 * 19; o += 256) {
        const int r = o / 19, j = o % 19;
        const float* wp = (j < 18) ? (aw + j * HID) : cw;
        const float bias = (j < 18) ? ab[j] : cb[0];
        const float4* h4 = (const float4*)(hsm + r * HID);
        const float4* w4 = (const float4*)wp;
        float acc = 0.f;
#pragma unroll 8
        for (int k = 0; k < HID / 4; k++) {
            const float4 hv = h4[k];
            const float4 wv = __ldg(&w4[k]);
            acc += hv.x*wv.x + hv.y*wv.y + hv.z*wv.z + hv.w*wv.w;
        }
        out[(size_t)(row0 + r) * 19 + j] = acc + bias;
    }
}

// ---------------- launch ----------------
extern "C" void kernel_launch(void* const* d_in, const int* in_sizes, int n_in,
                              void* d_out, int out_size) {
    const float* x    = (const float*)d_in[0];
    const float* done = (const float*)d_in[1];
    const float* h0   = (const float*)d_in[2];
    const float* c0   = (const float*)d_in[3];
    const float* c1w  = (const float*)d_in[4];
    const float* c1b  = (const float*)d_in[5];
    const float* c2w  = (const float*)d_in[6];
    const float* c2b  = (const float*)d_in[7];
    const float* c3w  = (const float*)d_in[8];
    const float* c3b  = (const float*)d_in[9];
    const float* fcw  = (const float*)d_in[10];
    const float* fcb  = (const float*)d_in[11];
    const float* wi   = (const float*)d_in[12];
    const float* wh   = (const float*)d_in[13];
    const float* bi   = (const float*)d_in[14];
    const float* bh   = (const float*)d_in[15];
    const float* aw   = (const float*)d_in[16];
    const float* ab   = (const float*)d_in[17];
    const float* cw   = (const float*)d_in[18];
    const float* cb   = (const float*)d_in[19];
    float* out = (float*)d_out;

    cudaFuncSetAttribute(conv1_kernel, cudaFuncAttributeMaxDynamicSharedMemorySize, 98304);

    float* out1;  cudaGetSymbolAddress((void**)&out1,  g_out1);
    float* out2;  cudaGetSymbolAddress((void**)&out2,  g_out2);
    float* out3;  cudaGetSymbolAddress((void**)&out3,  g_out3);
    float* feats; cudaGetSymbolAddress((void**)&feats, g_feats);
    float* gi;    cudaGetSymbolAddress((void**)&gi,    g_gi);
    float* gt;    cudaGetSymbolAddress((void**)&gt,    g_gt);
    float* outs;  cudaGetSymbolAddress((void**)&outs,  g_outs);
    float* w3p;   cudaGetSymbolAddress((void**)&w3p,   g_w3p);

    prep_w3<<<192, 256>>>(c3w);
    conv1_kernel<<<TN, 256, 98304>>>(x, c1w, c1b, out1);
    conv2_kernel<<<TN, 144>>>(out1, c2w, c2b, out2);
    conv3_kernel<<<TN / 4, 256>>>(out2, w3p, c3b, out3);
    gemm_nt<<<dim3(512 / 128, TN / 128), 256>>>(out3, fcw, fcb, nullptr, feats, TN, 512, 1024, 1);
    gemm_nt<<<dim3(1024 / 128, TN / 128), 256>>>(feats, wi, bi, bh, gi, TN, 1024, 512, 0);
    gi_transpose<<<dim3(TT, 32), dim3(32, 8)>>>(gi, gt);
    init_h_kernel<<<32, 256>>>(h0);
    lstm_kernel<<<NBLK_LSTM, 256>>>(gt, done, c0, wh, outs);
    heads_kernel<<<TN / 32, 256>>>(outs, aw, ab, cw, cb, out);
}